// round 8
// baseline (speedup 1.0000x reference)
#include <cuda_runtime.h>
#include <cuda_bf16.h>

#define NSAMPLE 32
#define MAXN 8192
#define RADIUS2 1.0f

// Scratch (no allocations allowed)
__device__ int g_ball[MAXN * NSAMPLE];
__device__ int g_cnt[MAXN];
__device__ int g_off[MAXN + 1];
__device__ int g_done = 0;

// sum of squares with explicit mul-then-left-assoc-add (no fma contraction),
// matching XLA's elementwise square + axis reduce.
__device__ __forceinline__ float sq3(float ax, float ay, float az) {
    return __fadd_rn(__fadd_rn(__fmul_rn(ax, ax), __fmul_rn(ay, ay)), __fmul_rn(az, az));
}

// ---------------------------------------------------------------------------
// Kernel 1: fused roi-mask + ordered ball query + count, with last-block scan.
// One warp per point. 2 warps / block (64 threads) for load balance.
// ---------------------------------------------------------------------------
__global__ void __launch_bounds__(64) query_scan_kernel(
        const float* __restrict__ xyz,
        const float* __restrict__ new_xyz,
        const float* __restrict__ rois,
        int N, int Nb, int M, int K) {
    int lane = threadIdx.x & 31;
    int wid  = threadIdx.x >> 5;           // 0..1
    int n    = blockIdx.x * 2 + wid;

    if (n < N) {
        int b = n / Nb;
        float px = xyz[3 * n + 0], py = xyz[3 * n + 1], pz = xyz[3 * n + 2];

        // --- roi membership bitmask via per-lane checks + ballot ---
        const float* r = rois + (size_t)b * M * 7;
        unsigned long long bm = 0ull;
        for (int mb = 0; mb < M; mb += 32) {
            int m = mb + lane;
            bool in = false;
            if (m < M) {
                float cx = r[m * 7 + 0], cy = r[m * 7 + 1], cz = r[m * 7 + 2];
                float dx = r[m * 7 + 3], dy = r[m * 7 + 4], dz = r[m * 7 + 5];
                float r2 = sq3(dx, dy, dz);
                float d2 = sq3(__fsub_rn(px, cx), __fsub_rn(py, cy), __fsub_rn(pz, cz));
                in = (d2 <= r2);
            }
            unsigned bits = __ballot_sync(0xffffffffu, in);
            bm |= ((unsigned long long)bits) << mb;
        }

        // --- ordered ball query: first NSAMPLE hits in j = m*K + k order ---
        int count = 0;
        int* outp = g_ball + n * NSAMPLE;
        int baseMK = b * M * K;
        while (bm && count < NSAMPLE) {
            int m = __ffsll((long long)bm) - 1;
            bm &= bm - 1ull;
            const float* g = new_xyz + ((size_t)(b * M + m)) * K * 3;
            for (int k0 = 0; k0 < K && count < NSAMPLE; k0 += 32) {
                int k = k0 + lane;
                bool ok = false;
                if (k < K) {
                    float gx = g[3 * k + 0], gy = g[3 * k + 1], gz = g[3 * k + 2];
                    float d2 = sq3(__fsub_rn(px, gx), __fsub_rn(py, gy), __fsub_rn(pz, gz));
                    ok = (d2 <= RADIUS2);
                }
                unsigned bits = __ballot_sync(0xffffffffu, ok);
                int rank = count + __popc(bits & ((1u << lane) - 1u));
                if (ok && rank < NSAMPLE) outp[rank] = baseMK + m * K + k;
                count += __popc(bits);
            }
        }
        if (lane == 0) {
            g_cnt[n] = count < NSAMPLE ? count : NSAMPLE;
            __threadfence();   // make this warp's cnt/ball globally visible
        }
    }

    // --- last-block-done: the final block performs the exclusive scan ---
    __shared__ int sh_isLast;
    __syncthreads();
    if (threadIdx.x == 0) {
        int t = atomicAdd(&g_done, 1);
        sh_isLast = (t == (int)gridDim.x - 1) ? 1 : 0;
    }
    __syncthreads();
    if (!sh_isLast) return;

    // Two-pass exclusive scan of g_cnt[0..N) -> g_off, g_off[N]=total. 64 thr.
    int tid = threadIdx.x;
    int per = (N + 63) / 64;             // <= 128 for MAXN=8192
    int base = tid * per;
    // pass 1: per-thread sum
    int s = 0;
    for (int i = 0; i < per; i++) {
        if (base + i < N) s += __ldcg(&g_cnt[base + i]);
    }
    // warp inclusive scan of per-thread sums
    int pre = s;
    #pragma unroll
    for (int d = 1; d < 32; d <<= 1) {
        int t = __shfl_up_sync(0xffffffffu, pre, d);
        if (lane >= d) pre += t;
    }
    __shared__ int wsum[2];
    if (lane == 31) wsum[wid] = pre;
    __syncthreads();
    int wbase = (wid == 1) ? wsum[0] : 0;
    // pass 2: re-read and write exclusive offsets
    int run = wbase + (pre - s);
    for (int i = 0; i < per; i++) {
        if (base + i < N) {
            int v = __ldcg(&g_cnt[base + i]);
            g_off[base + i] = run;
            run += v;
        }
    }
    if (tid == 63) g_off[N] = run;       // grand total
    if (tid == 0) g_done = 0;            // reset for next graph replay
}

// ---------------------------------------------------------------------------
// Kernel 2 (specialized W=35, C=32): warp-per-point flat coalesced gather
// with ALL loads hoisted out of the write loop (pure shfl + store inner loop),
// plus extra blocks that float4-zero the tail region concurrently.
// 2 warps / block (64 threads).
// ---------------------------------------------------------------------------
__global__ void __launch_bounds__(64) gather35_kernel(
        const float* __restrict__ xyz,
        const float* __restrict__ new_xyz,
        const float* __restrict__ feat,
        float* __restrict__ out_group,
        float* __restrict__ out_idx,
        int N, int has_idx, int point_blocks, int zero_blocks, int L) {
    const int W = 35, C = 32;
    int lane = threadIdx.x & 31;

    if ((int)blockIdx.x < point_blocks) {
        // ---------------- gather: one warp per point ----------------
        int n = blockIdx.x * 2 + (threadIdx.x >> 5);
        if (n >= N) return;
        int cnt = g_cnt[n];
        if (cnt == 0) return;
        int off = g_off[n];

        int gi_l = g_ball[n * NSAMPLE + (lane < cnt ? lane : 0)];
        if (has_idx && lane < cnt) out_idx[off + lane] = (float)gi_l;

        float px = xyz[3 * n + 0], py = xyz[3 * n + 1], pz = xyz[3 * n + 2];
        float fv = feat[(size_t)n * C + lane];          // C == 32: one per lane

        // per-lane slot deltas: lane s holds row s's xyz residual (hoisted!)
        float dxl = 0.f, dyl = 0.f, dzl = 0.f;
        if (lane < cnt) {
            const float* gp = new_xyz + 3 * (size_t)gi_l;
            dxl = __fsub_rn(px, __ldg(&gp[0]));
            dyl = __fsub_rn(py, __ldg(&gp[1]));
            dzl = __fsub_rn(pz, __ldg(&gp[2]));
        }

        int tot = cnt * W;                              // <= 1120
        float* base = out_group + (size_t)off * W;      // contiguous span
        int iters = (tot + 31) >> 5;
        #pragma unroll 2
        for (int it = 0; it < iters; it++) {
            int e = (it << 5) + lane;
            int s = (int)(((unsigned)e * 59919u) >> 21);   // e / 35 (exact for e<=1154)
            int c = e - s * W;
            int ss = s & 31;
            float vx = __shfl_sync(0xffffffffu, dxl, ss);
            float vy = __shfl_sync(0xffffffffu, dyl, ss);
            float vz = __shfl_sync(0xffffffffu, dzl, ss);
            float fc = __shfl_sync(0xffffffffu, fv, (c - 3) & 31);
            float v = (c == 0) ? vx : (c == 1) ? vy : (c == 2) ? vz : fc;
            if (e < tot) base[e] = v;
        }
    } else {
        // ---------------- zero the tail [total*W, L*W) ----------------
        int zb  = blockIdx.x - point_blocks;
        int tid = zb * 64 + threadIdx.x;
        int stride = zero_blocks * 64;
        int total = g_off[N];
        size_t start = (size_t)total * W;
        size_t end   = (size_t)L * W;
        if (start < end) {
            size_t start4 = (start + 3) & ~(size_t)3;   // out_group is 16B aligned
            if (start4 > end) start4 = end;
            // scalar head (<=3 elements)
            if (tid < (int)(start4 - start)) out_group[start + tid] = 0.f;
            // vector body
            float4 z4 = make_float4(0.f, 0.f, 0.f, 0.f);
            float4* o4 = (float4*)out_group;
            size_t i0 = start4 >> 2, i1 = end >> 2;
            for (size_t i = i0 + tid; i < i1; i += stride) o4[i] = z4;
            // scalar tail (<=3 elements)
            size_t rem = end & 3;
            if (tid < (int)rem) out_group[(i1 << 2) + tid] = 0.f;
        }
        if (has_idx) {
            for (int i = total + tid; i < L; i += stride) out_idx[i] = 0.f;
        }
    }
}

// ---------------------------------------------------------------------------
// Generic fallback gather (any W/C): warp per slot, row-wise (rarely used).
// ---------------------------------------------------------------------------
__global__ void __launch_bounds__(256) gather_generic_kernel(
        const float* __restrict__ xyz,
        const float* __restrict__ new_xyz,
        const float* __restrict__ feat,
        float* __restrict__ out_group,
        float* __restrict__ out_idx,
        int N, int C, int has_idx) {
    int gw   = (blockIdx.x * blockDim.x + threadIdx.x) >> 5;
    int lane = threadIdx.x & 31;
    int L = N * NSAMPLE;
    if (gw >= L) return;
    int total = g_off[N];
    int W = 3 + C;

    int n = gw >> 5;
    int s = gw & (NSAMPLE - 1);
    if (s < g_cnt[n]) {
        int pos = g_off[n] + s;
        int gi  = g_ball[n * NSAMPLE + s];
        float* row = out_group + (size_t)pos * W;
        for (int c = lane; c < W; c += 32) {
            float v;
            if (c < 3) v = __fsub_rn(xyz[3 * n + c], new_xyz[3 * (size_t)gi + c]);
            else       v = feat[(size_t)n * C + (c - 3)];
            row[c] = v;
        }
        if (lane == 0 && has_idx) out_idx[pos] = (float)gi;
    }
    if (gw >= total) {
        float* row = out_group + (size_t)gw * W;
        for (int c = lane; c < W; c += 32) row[c] = 0.f;
        if (lane == 0 && has_idx) out_idx[gw] = 0.f;
    }
}

// ---------------------------------------------------------------------------
extern "C" void kernel_launch(void* const* d_in, const int* in_sizes, int n_in,
                              void* d_out, int out_size) {
    const float* xyz      = (const float*)d_in[0];
    const float* new_xyz  = (const float*)d_in[2];
    const float* rois     = (const float*)d_in[3];
    const float* features = (const float*)d_in[4];

    int N  = in_sizes[0] / 3;
    int B  = in_sizes[1];
    int M  = in_sizes[3] / (7 * B);
    int K  = in_sizes[2] / (3 * B * M);
    int C  = in_sizes[4] / N;
    int Nb = N / B;
    int L  = N * NSAMPLE;
    int W  = 3 + C;

    float* out = (float*)d_out;
    int has_idx = (out_size >= L * W + L) ? 1 : 0;
    float* out_idx = out + (size_t)L * W;

    // 1. fused mask + ordered ball query + count + (last block) scan
    {
        int blocks = (N + 1) / 2;          // 2 warps per 64-thread block
        query_scan_kernel<<<blocks, 64>>>(xyz, new_xyz, rois, N, Nb, M, K);
    }
    // 2. fused gather + concurrent tail-zero
    if (C == 32) {
        int point_blocks = (N + 1) / 2;    // warp per point, 2 warps/block
        int zero_blocks  = 2048;
        gather35_kernel<<<point_blocks + zero_blocks, 64>>>(
            xyz, new_xyz, features, out, out_idx,
            N, has_idx, point_blocks, zero_blocks, L);
    } else {
        int blocks = (L * 32 + 255) / 256;
        gather_generic_kernel<<<blocks, 256>>>(xyz, new_xyz, features, out, out_idx,
                                               N, C, has_idx);
    }
}

// round 9
// speedup vs baseline: 1.5129x; 1.5129x over previous
#include <cuda_runtime.h>
#include <cuda_bf16.h>

#define NSAMPLE 32
#define MAXN 8192
#define RADIUS2 1.0f
#define MAXCH 8   // max 32-lane chunks of K supported by the batched path (K<=256)

// Scratch (no allocations allowed)
__device__ int g_ball[MAXN * NSAMPLE];
__device__ int g_cnt[MAXN];
__device__ int g_off[MAXN + 1];
__device__ int g_done = 0;

// sum of squares with explicit mul-then-left-assoc-add (no fma contraction),
// matching XLA's elementwise square + axis reduce.
__device__ __forceinline__ float sq3(float ax, float ay, float az) {
    return __fadd_rn(__fadd_rn(__fmul_rn(ax, ax), __fmul_rn(ay, ay)), __fmul_rn(az, az));
}

// ---------------------------------------------------------------------------
// Kernel 1: fused roi-mask + ordered ball query + count, with last-block scan.
// One warp per point, 8 warps / block. Grid points of each roi are batch-
// loaded into registers (high MLP) before the ballot loop.
// ---------------------------------------------------------------------------
__global__ void __launch_bounds__(256) query_scan_kernel(
        const float* __restrict__ xyz,
        const float* __restrict__ new_xyz,
        const float* __restrict__ rois,
        int N, int Nb, int M, int K) {
    int lane = threadIdx.x & 31;
    int wid  = threadIdx.x >> 5;
    int n    = blockIdx.x * 8 + wid;

    if (n < N) {
        int b = n / Nb;
        float px = xyz[3 * n + 0], py = xyz[3 * n + 1], pz = xyz[3 * n + 2];

        // --- roi membership bitmask via per-lane checks + ballot ---
        const float* r = rois + (size_t)b * M * 7;
        unsigned long long bm = 0ull;
        for (int mb = 0; mb < M; mb += 32) {
            int m = mb + lane;
            bool in = false;
            if (m < M) {
                float cx = r[m * 7 + 0], cy = r[m * 7 + 1], cz = r[m * 7 + 2];
                float dx = r[m * 7 + 3], dy = r[m * 7 + 4], dz = r[m * 7 + 5];
                float r2 = sq3(dx, dy, dz);
                float d2 = sq3(__fsub_rn(px, cx), __fsub_rn(py, cy), __fsub_rn(pz, cz));
                in = (d2 <= r2);
            }
            unsigned bits = __ballot_sync(0xffffffffu, in);
            bm |= ((unsigned long long)bits) << mb;
        }

        // --- ordered ball query: first NSAMPLE hits in j = m*K + k order ---
        int count = 0;
        int* outp = g_ball + n * NSAMPLE;
        int baseMK = b * M * K;
        int nch = (K + 31) >> 5;

        if (nch <= MAXCH) {
            while (bm && count < NSAMPLE) {
                int m = __ffsll((long long)bm) - 1;
                bm &= bm - 1ull;
                const float* g = new_xyz + ((size_t)(b * M + m)) * K * 3;

                // batch-load ALL grid points for this roi (independent loads)
                float gx[MAXCH], gy[MAXCH], gz[MAXCH];
                #pragma unroll
                for (int j = 0; j < MAXCH; j++) {
                    if (j < nch) {
                        int k = (j << 5) + lane;
                        int kc = k < K ? k : K - 1;     // clamp (masked later)
                        gx[j] = __ldg(&g[3 * kc + 0]);
                        gy[j] = __ldg(&g[3 * kc + 1]);
                        gz[j] = __ldg(&g[3 * kc + 2]);
                    }
                }
                // ballot loop entirely from registers
                #pragma unroll
                for (int j = 0; j < MAXCH; j++) {
                    if (j < nch && count < NSAMPLE) {
                        int k = (j << 5) + lane;
                        bool ok = false;
                        if (k < K) {
                            float d2 = sq3(__fsub_rn(px, gx[j]),
                                           __fsub_rn(py, gy[j]),
                                           __fsub_rn(pz, gz[j]));
                            ok = (d2 <= RADIUS2);
                        }
                        unsigned bits = __ballot_sync(0xffffffffu, ok);
                        int rank = count + __popc(bits & ((1u << lane) - 1u));
                        if (ok && rank < NSAMPLE) outp[rank] = baseMK + m * K + k;
                        count += __popc(bits);
                    }
                }
            }
        } else {
            // generic fallback (K > 32*MAXCH)
            while (bm && count < NSAMPLE) {
                int m = __ffsll((long long)bm) - 1;
                bm &= bm - 1ull;
                const float* g = new_xyz + ((size_t)(b * M + m)) * K * 3;
                for (int k0 = 0; k0 < K && count < NSAMPLE; k0 += 32) {
                    int k = k0 + lane;
                    bool ok = false;
                    if (k < K) {
                        float d2 = sq3(__fsub_rn(px, g[3 * k + 0]),
                                       __fsub_rn(py, g[3 * k + 1]),
                                       __fsub_rn(pz, g[3 * k + 2]));
                        ok = (d2 <= RADIUS2);
                    }
                    unsigned bits = __ballot_sync(0xffffffffu, ok);
                    int rank = count + __popc(bits & ((1u << lane) - 1u));
                    if (ok && rank < NSAMPLE) outp[rank] = baseMK + m * K + k;
                    count += __popc(bits);
                }
            }
        }
        if (lane == 0) {
            g_cnt[n] = count < NSAMPLE ? count : NSAMPLE;
            __threadfence();   // make this warp's cnt/ball globally visible
        }
    }

    // --- last-block-done: the final block performs the exclusive scan ---
    __shared__ int sh_isLast;
    __syncthreads();
    if (threadIdx.x == 0) {
        int t = atomicAdd(&g_done, 1);
        sh_isLast = (t == (int)gridDim.x - 1) ? 1 : 0;
    }
    __syncthreads();
    if (!sh_isLast) return;

    // scan of g_cnt[0..N) -> g_off (exclusive), g_off[N] = total. 256 threads.
    int tid = threadIdx.x;
    int per = (N + 255) / 256;           // <= 32 for MAXN=8192
    int base = tid * per;
    int loc[32];
    int s = 0;
    #pragma unroll 4
    for (int i = 0; i < per; i++) {
        int v = (base + i < N) ? __ldcg(&g_cnt[base + i]) : 0;
        loc[i] = v;
        s += v;
    }
    // warp inclusive scan of per-thread sums
    int pre = s;
    #pragma unroll
    for (int d = 1; d < 32; d <<= 1) {
        int t = __shfl_up_sync(0xffffffffu, pre, d);
        if (lane >= d) pre += t;
    }
    __shared__ int wsum[8];
    if (lane == 31) wsum[wid] = pre;
    __syncthreads();
    if (tid == 0) {
        int acc = 0;
        #pragma unroll
        for (int w = 0; w < 8; w++) { int t = wsum[w]; wsum[w] = acc; acc += t; }
    }
    __syncthreads();
    int run = wsum[wid] + (pre - s);     // exclusive prefix for this chunk
    #pragma unroll 4
    for (int i = 0; i < per; i++) {
        if (base + i < N) g_off[base + i] = run;
        run += loc[i];
    }
    if (tid == 255) g_off[N] = run;      // grand total (pads are zero)
    if (tid == 0) g_done = 0;            // reset for next graph replay
}

// ---------------------------------------------------------------------------
// Kernel 2 (specialized W=35, C=32): warp-per-point flat coalesced gather
// with ALL loads hoisted out of the write loop (pure shfl + store inner loop),
// plus extra blocks that float4-zero the tail region concurrently.
// 2 warps / block (64 threads).
// ---------------------------------------------------------------------------
__global__ void __launch_bounds__(64) gather35_kernel(
        const float* __restrict__ xyz,
        const float* __restrict__ new_xyz,
        const float* __restrict__ feat,
        float* __restrict__ out_group,
        float* __restrict__ out_idx,
        int N, int has_idx, int point_blocks, int zero_blocks, int L) {
    const int W = 35, C = 32;
    int lane = threadIdx.x & 31;

    if ((int)blockIdx.x < point_blocks) {
        // ---------------- gather: one warp per point ----------------
        int n = blockIdx.x * 2 + (threadIdx.x >> 5);
        if (n >= N) return;
        int cnt = g_cnt[n];
        if (cnt == 0) return;
        int off = g_off[n];

        int gi_l = g_ball[n * NSAMPLE + (lane < cnt ? lane : 0)];
        if (has_idx && lane < cnt) out_idx[off + lane] = (float)gi_l;

        float px = xyz[3 * n + 0], py = xyz[3 * n + 1], pz = xyz[3 * n + 2];
        float fv = feat[(size_t)n * C + lane];          // C == 32: one per lane

        // per-lane slot deltas: lane s holds row s's xyz residual (hoisted!)
        float dxl = 0.f, dyl = 0.f, dzl = 0.f;
        if (lane < cnt) {
            const float* gp = new_xyz + 3 * (size_t)gi_l;
            dxl = __fsub_rn(px, __ldg(&gp[0]));
            dyl = __fsub_rn(py, __ldg(&gp[1]));
            dzl = __fsub_rn(pz, __ldg(&gp[2]));
        }

        int tot = cnt * W;                              // <= 1120
        float* base = out_group + (size_t)off * W;      // contiguous span
        int iters = (tot + 31) >> 5;
        #pragma unroll 2
        for (int it = 0; it < iters; it++) {
            int e = (it << 5) + lane;
            int s = (int)(((unsigned)e * 59919u) >> 21);   // e / 35 (exact for e<=1154)
            int c = e - s * W;
            int ss = s & 31;
            float vx = __shfl_sync(0xffffffffu, dxl, ss);
            float vy = __shfl_sync(0xffffffffu, dyl, ss);
            float vz = __shfl_sync(0xffffffffu, dzl, ss);
            float fc = __shfl_sync(0xffffffffu, fv, (c - 3) & 31);
            float v = (c == 0) ? vx : (c == 1) ? vy : (c == 2) ? vz : fc;
            if (e < tot) base[e] = v;
        }
    } else {
        // ---------------- zero the tail [total*W, L*W) ----------------
        int zb  = blockIdx.x - point_blocks;
        int tid = zb * 64 + threadIdx.x;
        int stride = zero_blocks * 64;
        int total = g_off[N];
        size_t start = (size_t)total * W;
        size_t end   = (size_t)L * W;
        if (start < end) {
            size_t start4 = (start + 3) & ~(size_t)3;   // out_group is 16B aligned
            if (start4 > end) start4 = end;
            // scalar head (<=3 elements)
            if (tid < (int)(start4 - start)) out_group[start + tid] = 0.f;
            // vector body
            float4 z4 = make_float4(0.f, 0.f, 0.f, 0.f);
            float4* o4 = (float4*)out_group;
            size_t i0 = start4 >> 2, i1 = end >> 2;
            for (size_t i = i0 + tid; i < i1; i += stride) o4[i] = z4;
            // scalar tail (<=3 elements)
            size_t rem = end & 3;
            if (tid < (int)rem) out_group[(i1 << 2) + tid] = 0.f;
        }
        if (has_idx) {
            for (int i = total + tid; i < L; i += stride) out_idx[i] = 0.f;
        }
    }
}

// ---------------------------------------------------------------------------
// Generic fallback gather (any W/C): warp per slot, row-wise (rarely used).
// ---------------------------------------------------------------------------
__global__ void __launch_bounds__(256) gather_generic_kernel(
        const float* __restrict__ xyz,
        const float* __restrict__ new_xyz,
        const float* __restrict__ feat,
        float* __restrict__ out_group,
        float* __restrict__ out_idx,
        int N, int C, int has_idx) {
    int gw   = (blockIdx.x * blockDim.x + threadIdx.x) >> 5;
    int lane = threadIdx.x & 31;
    int L = N * NSAMPLE;
    if (gw >= L) return;
    int total = g_off[N];
    int W = 3 + C;

    int n = gw >> 5;
    int s = gw & (NSAMPLE - 1);
    if (s < g_cnt[n]) {
        int pos = g_off[n] + s;
        int gi  = g_ball[n * NSAMPLE + s];
        float* row = out_group + (size_t)pos * W;
        for (int c = lane; c < W; c += 32) {
            float v;
            if (c < 3) v = __fsub_rn(xyz[3 * n + c], new_xyz[3 * (size_t)gi + c]);
            else       v = feat[(size_t)n * C + (c - 3)];
            row[c] = v;
        }
        if (lane == 0 && has_idx) out_idx[pos] = (float)gi;
    }
    if (gw >= total) {
        float* row = out_group + (size_t)gw * W;
        for (int c = lane; c < W; c += 32) row[c] = 0.f;
        if (lane == 0 && has_idx) out_idx[gw] = 0.f;
    }
}

// ---------------------------------------------------------------------------
extern "C" void kernel_launch(void* const* d_in, const int* in_sizes, int n_in,
                              void* d_out, int out_size) {
    const float* xyz      = (const float*)d_in[0];
    const float* new_xyz  = (const float*)d_in[2];
    const float* rois     = (const float*)d_in[3];
    const float* features = (const float*)d_in[4];

    int N  = in_sizes[0] / 3;
    int B  = in_sizes[1];
    int M  = in_sizes[3] / (7 * B);
    int K  = in_sizes[2] / (3 * B * M);
    int C  = in_sizes[4] / N;
    int Nb = N / B;
    int L  = N * NSAMPLE;
    int W  = 3 + C;

    float* out = (float*)d_out;
    int has_idx = (out_size >= L * W + L) ? 1 : 0;
    float* out_idx = out + (size_t)L * W;

    // 1. fused mask + ordered ball query + count + (last block) scan
    {
        int blocks = (N + 7) / 8;          // 8 warps per 256-thread block
        query_scan_kernel<<<blocks, 256>>>(xyz, new_xyz, rois, N, Nb, M, K);
    }
    // 2. fused gather + concurrent tail-zero
    if (C == 32) {
        int point_blocks = (N + 1) / 2;    // warp per point, 2 warps/block
        int zero_blocks  = 2048;
        gather35_kernel<<<point_blocks + zero_blocks, 64>>>(
            xyz, new_xyz, features, out, out_idx,
            N, has_idx, point_blocks, zero_blocks, L);
    } else {
        int blocks = (L * 32 + 255) / 256;
        gather_generic_kernel<<<blocks, 256>>>(xyz, new_xyz, features, out, out_idx,
                                               N, C, has_idx);
    }
}

// round 11
// speedup vs baseline: 1.8395x; 1.2159x over previous
#include <cuda_runtime.h>
#include <cuda_bf16.h>

#define NSAMPLE 32
#define MAXN 8192
#define RADIUS2 1.0f
#define MAXCH 8   // max 32-lane chunks of K supported by the batched path (K<=256)

// Scratch (no allocations allowed)
__device__ int g_ball[MAXN * NSAMPLE];
__device__ int g_cnt[MAXN];
__device__ int g_off[MAXN + 1];
__device__ int g_done = 0;

// sum of squares with explicit mul-then-left-assoc-add (no fma contraction),
// matching XLA's elementwise square + axis reduce.
__device__ __forceinline__ float sq3(float ax, float ay, float az) {
    return __fadd_rn(__fadd_rn(__fmul_rn(ax, ax), __fmul_rn(ay, ay)), __fmul_rn(az, az));
}

// ---------------------------------------------------------------------------
// Kernel 1: fused roi-mask + ordered ball query + count, with last-block scan.
// One warp per point, 8 warps / block. Grid points of each roi are batch-
// loaded into registers (high MLP) before the ballot loop.
// ---------------------------------------------------------------------------
__global__ void __launch_bounds__(256) query_scan_kernel(
        const float* __restrict__ xyz,
        const float* __restrict__ new_xyz,
        const float* __restrict__ rois,
        int N, int Nb, int M, int K) {
    int lane = threadIdx.x & 31;
    int wid  = threadIdx.x >> 5;
    int n    = blockIdx.x * 8 + wid;

    if (n < N) {
        int b = n / Nb;
        float px = xyz[3 * n + 0], py = xyz[3 * n + 1], pz = xyz[3 * n + 2];

        // --- roi membership bitmask via per-lane checks + ballot ---
        const float* r = rois + (size_t)b * M * 7;
        unsigned long long bm = 0ull;
        for (int mb = 0; mb < M; mb += 32) {
            int m = mb + lane;
            bool in = false;
            if (m < M) {
                float cx = r[m * 7 + 0], cy = r[m * 7 + 1], cz = r[m * 7 + 2];
                float dx = r[m * 7 + 3], dy = r[m * 7 + 4], dz = r[m * 7 + 5];
                float r2 = sq3(dx, dy, dz);
                float d2 = sq3(__fsub_rn(px, cx), __fsub_rn(py, cy), __fsub_rn(pz, cz));
                in = (d2 <= r2);
            }
            unsigned bits = __ballot_sync(0xffffffffu, in);
            bm |= ((unsigned long long)bits) << mb;
        }

        // --- ordered ball query: first NSAMPLE hits in j = m*K + k order ---
        int count = 0;
        int* outp = g_ball + n * NSAMPLE;
        int baseMK = b * M * K;
        int nch = (K + 31) >> 5;

        if (nch <= MAXCH) {
            while (bm && count < NSAMPLE) {
                int m = __ffsll((long long)bm) - 1;
                bm &= bm - 1ull;
                const float* g = new_xyz + ((size_t)(b * M + m)) * K * 3;

                // batch-load ALL grid points for this roi (independent loads)
                float gx[MAXCH], gy[MAXCH], gz[MAXCH];
                #pragma unroll
                for (int j = 0; j < MAXCH; j++) {
                    if (j < nch) {
                        int k = (j << 5) + lane;
                        int kc = k < K ? k : K - 1;     // clamp (masked later)
                        gx[j] = __ldg(&g[3 * kc + 0]);
                        gy[j] = __ldg(&g[3 * kc + 1]);
                        gz[j] = __ldg(&g[3 * kc + 2]);
                    }
                }
                // ballot loop entirely from registers
                #pragma unroll
                for (int j = 0; j < MAXCH; j++) {
                    if (j < nch && count < NSAMPLE) {
                        int k = (j << 5) + lane;
                        bool ok = false;
                        if (k < K) {
                            float d2 = sq3(__fsub_rn(px, gx[j]),
                                           __fsub_rn(py, gy[j]),
                                           __fsub_rn(pz, gz[j]));
                            ok = (d2 <= RADIUS2);
                        }
                        unsigned bits = __ballot_sync(0xffffffffu, ok);
                        int rank = count + __popc(bits & ((1u << lane) - 1u));
                        if (ok && rank < NSAMPLE) outp[rank] = baseMK + m * K + k;
                        count += __popc(bits);
                    }
                }
            }
        } else {
            // generic fallback (K > 32*MAXCH)
            while (bm && count < NSAMPLE) {
                int m = __ffsll((long long)bm) - 1;
                bm &= bm - 1ull;
                const float* g = new_xyz + ((size_t)(b * M + m)) * K * 3;
                for (int k0 = 0; k0 < K && count < NSAMPLE; k0 += 32) {
                    int k = k0 + lane;
                    bool ok = false;
                    if (k < K) {
                        float d2 = sq3(__fsub_rn(px, g[3 * k + 0]),
                                       __fsub_rn(py, g[3 * k + 1]),
                                       __fsub_rn(pz, g[3 * k + 2]));
                        ok = (d2 <= RADIUS2);
                    }
                    unsigned bits = __ballot_sync(0xffffffffu, ok);
                    int rank = count + __popc(bits & ((1u << lane) - 1u));
                    if (ok && rank < NSAMPLE) outp[rank] = baseMK + m * K + k;
                    count += __popc(bits);
                }
            }
        }
        if (lane == 0) {
            g_cnt[n] = count < NSAMPLE ? count : NSAMPLE;
            __threadfence();   // make this warp's cnt/ball globally visible
        }
    }

    // --- last-block-done: the final block performs the exclusive scan ---
    __shared__ int sh_isLast;
    __syncthreads();
    if (threadIdx.x == 0) {
        int t = atomicAdd(&g_done, 1);
        sh_isLast = (t == (int)gridDim.x - 1) ? 1 : 0;
    }
    __syncthreads();
    if (!sh_isLast) return;

    // scan of g_cnt[0..N) -> g_off (exclusive), g_off[N] = total. 256 threads.
    int tid = threadIdx.x;
    int per = (N + 255) / 256;           // <= 32 for MAXN=8192
    int base = tid * per;
    int loc[32];
    int s = 0;
    #pragma unroll 4
    for (int i = 0; i < per; i++) {
        int v = (base + i < N) ? __ldcg(&g_cnt[base + i]) : 0;
        loc[i] = v;
        s += v;
    }
    // warp inclusive scan of per-thread sums
    int pre = s;
    #pragma unroll
    for (int d = 1; d < 32; d <<= 1) {
        int t = __shfl_up_sync(0xffffffffu, pre, d);
        if (lane >= d) pre += t;
    }
    __shared__ int wsum[8];
    if (lane == 31) wsum[wid] = pre;
    __syncthreads();
    if (tid == 0) {
        int acc = 0;
        #pragma unroll
        for (int w = 0; w < 8; w++) { int t = wsum[w]; wsum[w] = acc; acc += t; }
    }
    __syncthreads();
    int run = wsum[wid] + (pre - s);     // exclusive prefix for this chunk
    #pragma unroll 4
    for (int i = 0; i < per; i++) {
        if (base + i < N) g_off[base + i] = run;
        run += loc[i];
    }
    if (tid == 255) g_off[N] = run;      // grand total (pads are zero)
    if (tid == 0) g_done = 0;            // reset for next graph replay
}

// ---------------------------------------------------------------------------
// Kernel 2 (specialized W=35, C=32): warp-per-point gather exploiting the
// row-constant feature block: row s of a point is [dx_s,dy_s,dz_s, f0..f31],
// so columns 3..34 are one coalesced store of the lane-resident feature value
// per row (no shfl, no division). Residual columns 0..2 are a tiny scattered
// fixup from hoisted per-lane deltas. Extra blocks float4-zero the tail.
// 2 warps / block (64 threads).
// ---------------------------------------------------------------------------
__global__ void __launch_bounds__(64) gather35_kernel(
        const float* __restrict__ xyz,
        const float* __restrict__ new_xyz,
        const float* __restrict__ feat,
        float* __restrict__ out_group,
        float* __restrict__ out_idx,
        int N, int has_idx, int point_blocks, int zero_blocks, int L) {
    const int W = 35, C = 32;
    int lane = threadIdx.x & 31;

    if ((int)blockIdx.x < point_blocks) {
        // ---------------- gather: one warp per point ----------------
        int n = blockIdx.x * 2 + (threadIdx.x >> 5);
        if (n >= N) return;
        int cnt = g_cnt[n];
        if (cnt == 0) return;
        int off = g_off[n];

        int gi_l = g_ball[n * NSAMPLE + (lane < cnt ? lane : 0)];
        if (has_idx && lane < cnt) out_idx[off + lane] = (float)gi_l;

        float px = xyz[3 * n + 0], py = xyz[3 * n + 1], pz = xyz[3 * n + 2];
        float fv = feat[(size_t)n * C + lane];          // C == 32: one per lane

        // per-lane slot deltas: lane s holds row s's xyz residual (hoisted)
        float dxl = 0.f, dyl = 0.f, dzl = 0.f;
        if (lane < cnt) {
            const float* gp = new_xyz + 3 * (size_t)gi_l;
            dxl = __fsub_rn(px, __ldg(&gp[0]));
            dyl = __fsub_rn(py, __ldg(&gp[1]));
            dzl = __fsub_rn(pz, __ldg(&gp[2]));
        }

        float* base = out_group + (size_t)off * W;      // contiguous span
        // feature block: one coalesced 128B store per row, value is
        // lane-resident. rows are independent -> fully pipelined stores.
        float* p = base + 3 + lane;
        #pragma unroll 4
        for (int s = 0; s < cnt; s++) {
            *p = fv;
            p += W;
        }
        // residual fixup: lane s writes its row's 3 xyz deltas (disjoint
        // addresses from the feature block; no intra-warp race).
        if (lane < cnt) {
            float* r = base + lane * W;
            r[0] = dxl; r[1] = dyl; r[2] = dzl;
        }
    } else {
        // ---------------- zero the tail [total*W, L*W) ----------------
        int zb  = blockIdx.x - point_blocks;
        int tid = zb * 64 + threadIdx.x;
        int stride = zero_blocks * 64;
        int total = g_off[N];
        size_t start = (size_t)total * W;
        size_t end   = (size_t)L * W;
        if (start < end) {
            size_t start4 = (start + 3) & ~(size_t)3;   // out_group is 16B aligned
            if (start4 > end) start4 = end;
            // scalar head (<=3 elements)
            if (tid < (int)(start4 - start)) out_group[start + tid] = 0.f;
            // vector body
            float4 z4 = make_float4(0.f, 0.f, 0.f, 0.f);
            float4* o4 = (float4*)out_group;
            size_t i0 = start4 >> 2, i1 = end >> 2;
            for (size_t i = i0 + tid; i < i1; i += stride) o4[i] = z4;
            // scalar tail (<=3 elements)
            size_t rem = end & 3;
            if (tid < (int)rem) out_group[(i1 << 2) + tid] = 0.f;
        }
        if (has_idx) {
            for (int i = total + tid; i < L; i += stride) out_idx[i] = 0.f;
        }
    }
}

// ---------------------------------------------------------------------------
// Generic fallback gather (any W/C): warp per slot, row-wise (rarely used).
// ---------------------------------------------------------------------------
__global__ void __launch_bounds__(256) gather_generic_kernel(
        const float* __restrict__ xyz,
        const float* __restrict__ new_xyz,
        const float* __restrict__ feat,
        float* __restrict__ out_group,
        float* __restrict__ out_idx,
        int N, int C, int has_idx) {
    int gw   = (blockIdx.x * blockDim.x + threadIdx.x) >> 5;
    int lane = threadIdx.x & 31;
    int L = N * NSAMPLE;
    if (gw >= L) return;
    int total = g_off[N];
    int W = 3 + C;

    int n = gw >> 5;
    int s = gw & (NSAMPLE - 1);
    if (s < g_cnt[n]) {
        int pos = g_off[n] + s;
        int gi  = g_ball[n * NSAMPLE + s];
        float* row = out_group + (size_t)pos * W;
        for (int c = lane; c < W; c += 32) {
            float v;
            if (c < 3) v = __fsub_rn(xyz[3 * n + c], new_xyz[3 * (size_t)gi + c]);
            else       v = feat[(size_t)n * C + (c - 3)];
            row[c] = v;
        }
        if (lane == 0 && has_idx) out_idx[pos] = (float)gi;
    }
    if (gw >= total) {
        float* row = out_group + (size_t)gw * W;
        for (int c = lane; c < W; c += 32) row[c] = 0.f;
        if (lane == 0 && has_idx) out_idx[gw] = 0.f;
    }
}

// ---------------------------------------------------------------------------
extern "C" void kernel_launch(void* const* d_in, const int* in_sizes, int n_in,
                              void* d_out, int out_size) {
    const float* xyz      = (const float*)d_in[0];
    const float* new_xyz  = (const float*)d_in[2];
    const float* rois     = (const float*)d_in[3];
    const float* features = (const float*)d_in[4];

    int N  = in_sizes[0] / 3;
    int B  = in_sizes[1];
    int M  = in_sizes[3] / (7 * B);
    int K  = in_sizes[2] / (3 * B * M);
    int C  = in_sizes[4] / N;
    int Nb = N / B;
    int L  = N * NSAMPLE;
    int W  = 3 + C;

    float* out = (float*)d_out;
    int has_idx = (out_size >= L * W + L) ? 1 : 0;
    float* out_idx = out + (size_t)L * W;

    // 1. fused mask + ordered ball query + count + (last block) scan
    {
        int blocks = (N + 7) / 8;          // 8 warps per 256-thread block
        query_scan_kernel<<<blocks, 256>>>(xyz, new_xyz, rois, N, Nb, M, K);
    }
    // 2. fused gather + concurrent tail-zero
    if (C == 32) {
        int point_blocks = (N + 1) / 2;    // warp per point, 2 warps/block
        int zero_blocks  = 2048;
        gather35_kernel<<<point_blocks + zero_blocks, 64>>>(
            xyz, new_xyz, features, out, out_idx,
            N, has_idx, point_blocks, zero_blocks, L);
    } else {
        int blocks = (L * 32 + 255) / 256;
        gather_generic_kernel<<<blocks, 256>>>(xyz, new_xyz, features, out, out_idx,
                                               N, C, has_idx);
    }
}